// round 12
// baseline (speedup 1.0000x reference)
#include <cuda_runtime.h>
#include <cstdint>

#define B_  64
#define OH_ 120
#define OW_ 160
#define HW_ (OH_ * OW_)          // 19200
#define TOTAL_ (B_ * HW_)        // 1,228,800
#define IN_H_ 480.0f
#define IN_W_ 640.0f
#define THRESH_ 0.5f

#define NT  256                  // 8 warps
#define PPT 2                    // pixels per thread
#define PPW 64                   // pixels per warp
#define PPB (NT * PPT)           // 512 pixels per block

// SW128-style xor swizzle: permutes 16B chunks within 1024B, kills the
// stride-40B (2-way) and stride-80B (4-way) staging bank conflicts while
// keeping the flush LDS.128 conflict-free. Preserves bits[0:3] (alignment).
#define SW_(o) ((o) ^ (((o) >> 3) & 0x70))

// 8 CTAs/SM: 8*20KB = 160KB smem, 8*256*32 = 65536 regs -> 64 warps
__global__ __launch_bounds__(NT, 8)
void centerface_decode_kernel(const float* __restrict__ heatmap,   // [B,1,OH,OW]
                              const float* __restrict__ scale,     // [B,2,OH,OW]
                              const float* __restrict__ offset,    // [B,2,OH,OW]
                              const float* __restrict__ landmark,  // [B,10,OH,OW]
                              float* __restrict__ boxes,           // [B,HW,5]
                              float* __restrict__ lms,             // [B,HW,10]
                              float* __restrict__ keep)            // [B,HW]
{
    // One reusable staging buffer per warp: 640 floats = 2.5 KB (16B-multiple
    // stride so every warp slice stays 16B aligned).
    __shared__ __align__(16) float buf[8][PPW * 10];   // 20 KB

    const int tid  = threadIdx.x;
    const int wid  = tid >> 5;
    const int lane = tid & 31;

    const int base     = blockIdx.x * PPB;
    const int warpbase = base + wid * PPW;
    const int idx0     = warpbase + lane * PPT;

    const int b  = idx0 / HW_;
    const int p0 = idx0 - b * HW_;
    const int y  = p0 / OW_;
    const float yf = (float)y;

    char* wb = (char*)buf[wid];          // this warp's staging region

    // ---- vector loads (cached: inputs stay L2-resident across graph replays) ----
    union F2 { float2 v; float a[2]; };
    F2 hm, sc0, sc1, o0;
    hm.v  = *(const float2*)(heatmap + idx0);
    const float* scp = scale + (size_t)b * (2 * HW_) + p0;
    sc0.v = *(const float2*)(scp);
    sc1.v = *(const float2*)(scp + HW_);
    o0.v  = *(const float2*)(offset + (size_t)b * (2 * HW_) + p0);

    F2 lm[10];
    const float* lmp = landmark + (size_t)b * (10 * HW_) + p0;
#pragma unroll
    for (int j = 0; j < 10; j++)
        lm[j].v = *(const float2*)(lmp + (size_t)j * HW_);

    // ---- per-pixel compute, stage boxes (swizzled STS: conflict-free) ----
    F2 kp;
    float s0q[PPT], s1q[PPT], y1q[PPT], x1q[PPT], mq[PPT];

    const int bb = lane * 40;            // byte offset of this thread's box records

#pragma unroll
    for (int q = 0; q < PPT; q++) {
        float s0 = __expf(sc0.a[q]) * 4.0f;
        float s1 = __expf(sc1.a[q]) * 4.0f;

        float y1_raw = (yf + o0.a[q] + 0.5f) * 4.0f - s0 * 0.5f;
        float y1c = fmaxf(y1_raw, 0.0f);
        float y1  = fminf(y1c, IN_H_);
        float x1  = fminf(y1c, IN_W_);
        float y2  = fminf(y1 + s0, IN_H_);
        float x2  = fminf(x1 + s1, IN_W_);

        float h = hm.a[q];
        float m = (h >= THRESH_) ? 1.0f : 0.0f;
        kp.a[q] = m;

        s0q[q] = s0; s1q[q] = s1; y1q[q] = y1; x1q[q] = x1; mq[q] = m;

        if (q == 0) {
            *(float2*)(wb + SW_(bb + 0))  = make_float2(x1 * m, y1 * m);
            *(float2*)(wb + SW_(bb + 8))  = make_float2(x2 * m, y2 * m);
            *(float*) (wb + SW_(bb + 16)) = h * m;
        } else {
            *(float*) (wb + SW_(bb + 20)) = x1 * m;
            *(float2*)(wb + SW_(bb + 24)) = make_float2(y1 * m, x2 * m);
            *(float2*)(wb + SW_(bb + 32)) = make_float2(y2 * m, h * m);
        }
    }

    // keep: coalesced STG.64
    *(float2*)(keep + idx0) = kp.v;

    __syncwarp();

    // ---- flush boxes: 80 float4 per warp (swizzled LDS, streaming STG) ----
    {
        float4* dst = (float4*)(boxes + (size_t)warpbase * 5);
        __stcs(dst + lane,      *(const float4*)(wb + SW_(16 * lane)));
        __stcs(dst + 32 + lane, *(const float4*)(wb + SW_(16 * (32 + lane))));
        if (lane < 16)
            __stcs(dst + 64 + lane, *(const float4*)(wb + SW_(16 * (64 + lane))));
    }

    __syncwarp();   // WAR: box region fully read before landmark overwrite

    // ---- stage landmarks (swizzled STS: 4-way conflict -> conflict-free) ----
    {
        const int lb = lane * 80;        // byte offset of this thread's lm records
#pragma unroll
        for (int q = 0; q < PPT; q++) {
            float s0 = s0q[q], s1 = s1q[q], y1 = y1q[q], x1 = x1q[q], m = mq[q];
#pragma unroll
            for (int j = 0; j < 10; j += 2) {
                float ly = fmaf(lm[j].a[q],     s0, y1) * m;
                float lx = fmaf(lm[j + 1].a[q], s1, x1) * m;
                *(float2*)(wb + SW_(lb + 8 * (q * 5 + (j >> 1)))) = make_float2(ly, lx);
            }
        }
    }

    __syncwarp();

    // ---- flush landmarks: 160 float4 per warp (swizzled LDS, streaming STG) ----
    {
        float4* dst = (float4*)(lms + (size_t)warpbase * 10);
#pragma unroll
        for (int i = 0; i < 5; i++)
            __stcs(dst + i * 32 + lane,
                   *(const float4*)(wb + SW_(16 * (i * 32 + lane))));
    }
}

extern "C" void kernel_launch(void* const* d_in, const int* in_sizes, int n_in,
                              void* d_out, int out_size)
{
    const float* heatmap  = (const float*)d_in[0];
    const float* scale    = (const float*)d_in[1];
    const float* offset   = (const float*)d_in[2];
    const float* landmark = (const float*)d_in[3];

    float* out   = (float*)d_out;
    float* boxes = out;                          // [B,HW,5]
    float* lms   = out + (size_t)TOTAL_ * 5;     // [B,HW,10]
    float* keep  = out + (size_t)TOTAL_ * 15;    // [B,HW]

    int blocks = TOTAL_ / PPB;                   // 2400
    centerface_decode_kernel<<<blocks, NT>>>(heatmap, scale, offset, landmark,
                                             boxes, lms, keep);
}

// round 13
// speedup vs baseline: 1.1750x; 1.1750x over previous
#include <cuda_runtime.h>
#include <cstdint>

#define B_  64
#define OH_ 120
#define OW_ 160
#define HW_ (OH_ * OW_)          // 19200
#define TOTAL_ (B_ * HW_)        // 1,228,800
#define IN_H_ 480.0f
#define IN_W_ 640.0f
#define THRESH_ 0.5f

#define NT  128                  // 4 warps
#define NW  (NT / 32)
#define PPT 2                    // pixels per thread
#define PPW 64                   // pixels per warp
#define PPB (NT * PPT)           // 256 pixels per block

// 16 CTAs/SM: 16*10KB = 160KB smem, 16*128*32 = 65536 regs -> 64 warps (100%)
__global__ __launch_bounds__(NT, 16)
void centerface_decode_kernel(const float* __restrict__ heatmap,   // [B,1,OH,OW]
                              const float* __restrict__ scale,     // [B,2,OH,OW]
                              const float* __restrict__ offset,    // [B,2,OH,OW]
                              const float* __restrict__ landmark,  // [B,10,OH,OW]
                              float* __restrict__ boxes,           // [B,HW,5]
                              float* __restrict__ lms,             // [B,HW,10]
                              float* __restrict__ keep)            // [B,HW]
{
    // One reusable staging buffer per warp: 640 floats = 2.5 KB.
    // Phase 1: boxes (first 1280 B). Phase 2: landmarks (all 2560 B).
    __shared__ float buf[NW][PPW * 10];     // 10 KB

    const int tid  = threadIdx.x;
    const int wid  = tid >> 5;
    const int lane = tid & 31;

    const int base     = blockIdx.x * PPB;
    const int warpbase = base + wid * PPW;
    const int idx0     = warpbase + lane * PPT;

    const int b  = idx0 / HW_;
    const int p0 = idx0 - b * HW_;
    const int y  = p0 / OW_;
    const float yf = (float)y;

    // ---- vector loads (cached: inputs stay L2-resident across graph replays) ----
    union F2 { float2 v; float a[2]; };
    F2 hm, sc0, sc1, o0;
    hm.v  = *(const float2*)(heatmap + idx0);
    const float* scp = scale + (size_t)b * (2 * HW_) + p0;
    sc0.v = *(const float2*)(scp);
    sc1.v = *(const float2*)(scp + HW_);
    o0.v  = *(const float2*)(offset + (size_t)b * (2 * HW_) + p0);

    F2 lm[10];
    const float* lmp = landmark + (size_t)b * (10 * HW_) + p0;
#pragma unroll
    for (int j = 0; j < 10; j++)
        lm[j].v = *(const float2*)(lmp + (size_t)j * HW_);

    // ---- per-pixel compute, stage boxes ----
    F2 kp;
    float s0q[PPT], s1q[PPT], y1q[PPT], x1q[PPT], mq[PPT];

    float* bs = buf[wid] + lane * (5 * PPT);     // 10 contiguous floats

#pragma unroll
    for (int q = 0; q < PPT; q++) {
        float s0 = __expf(sc0.a[q]) * 4.0f;
        float s1 = __expf(sc1.a[q]) * 4.0f;

        float y1_raw = (yf + o0.a[q] + 0.5f) * 4.0f - s0 * 0.5f;
        float y1c = fmaxf(y1_raw, 0.0f);
        float y1  = fminf(y1c, IN_H_);
        float x1  = fminf(y1c, IN_W_);
        float y2  = fminf(y1 + s0, IN_H_);
        float x2  = fminf(x1 + s1, IN_W_);

        float h = hm.a[q];
        float m = (h >= THRESH_) ? 1.0f : 0.0f;
        kp.a[q] = m;

        s0q[q] = s0; s1q[q] = s1; y1q[q] = y1; x1q[q] = x1; mq[q] = m;

        // stage box record (vector STS where alignment allows: bs 8B-aligned)
        float2* bq2 = (float2*)(bs + q * 5 + (q & 1));
        if (q == 0) {
            bq2[0] = make_float2(x1 * m, y1 * m);
            bq2[1] = make_float2(x2 * m, y2 * m);
            bs[4]  = h * m;
        } else {
            bs[5]  = x1 * m;
            bq2[0] = make_float2(y1 * m, x2 * m);
            bq2[1] = make_float2(y2 * m, h * m);
        }
    }

    // keep: coalesced STG.64
    *(float2*)(keep + idx0) = kp.v;

    __syncwarp();

    // ---- flush boxes: 80 float4 per warp (streaming: evict-first) ----
    {
        const float4* src = (const float4*)buf[wid];
        float4*       dst = (float4*)(boxes + (size_t)warpbase * 5);
        __stcs(dst + lane,      src[lane]);
        __stcs(dst + 32 + lane, src[32 + lane]);
        if (lane < 16) __stcs(dst + 64 + lane, src[64 + lane]);
    }

    __syncwarp();   // WAR: box region fully read before landmark overwrite

    // ---- stage landmarks into same buffer ----
    {
        float2* ls = (float2*)(buf[wid] + lane * (10 * PPT));  // 20 floats
#pragma unroll
        for (int q = 0; q < PPT; q++) {
            float s0 = s0q[q], s1 = s1q[q], y1 = y1q[q], x1 = x1q[q], m = mq[q];
#pragma unroll
            for (int j = 0; j < 10; j += 2) {
                float ly = fmaf(lm[j].a[q],     s0, y1) * m;
                float lx = fmaf(lm[j + 1].a[q], s1, x1) * m;
                ls[q * 5 + (j >> 1)] = make_float2(ly, lx);
            }
        }
    }

    __syncwarp();

    // ---- flush landmarks: 160 float4 per warp (streaming) ----
    {
        const float4* src = (const float4*)buf[wid];
        float4*       dst = (float4*)(lms + (size_t)warpbase * 10);
#pragma unroll
        for (int i = 0; i < 5; i++)
            __stcs(dst + i * 32 + lane, src[i * 32 + lane]);
    }
}

extern "C" void kernel_launch(void* const* d_in, const int* in_sizes, int n_in,
                              void* d_out, int out_size)
{
    const float* heatmap  = (const float*)d_in[0];
    const float* scale    = (const float*)d_in[1];
    const float* offset   = (const float*)d_in[2];
    const float* landmark = (const float*)d_in[3];

    float* out   = (float*)d_out;
    float* boxes = out;                          // [B,HW,5]
    float* lms   = out + (size_t)TOTAL_ * 5;     // [B,HW,10]
    float* keep  = out + (size_t)TOTAL_ * 15;    // [B,HW]

    int blocks = TOTAL_ / PPB;                   // 4800
    centerface_decode_kernel<<<blocks, NT>>>(heatmap, scale, offset, landmark,
                                             boxes, lms, keep);
}